// round 1
// baseline (speedup 1.0000x reference)
#include <cuda_runtime.h>
#include <cuda_fp16.h>
#include <stdint.h>

// Problem dims
#define T_STEPS 4
#define B_DIM   64
#define N_DIM   196
#define D_DIM   512
#define C_DIM   1000
#define C_PAD   1024
#define BND     (B_DIM * N_DIM * D_DIM)        // 6,422,528
#define M_ROWS  (T_STEPS * B_DIM * N_DIM)      // 50,176  (divisible by 128)

// Scratch: fp16 spikes [M_ROWS, D] and fp16 W padded [C_PAD, D]
__device__ __half g_spk[(size_t)T_STEPS * BND];
__device__ __half g_wh[(size_t)C_PAD * D_DIM];

static __device__ __forceinline__ uint32_t smem_u32(const void* p) {
    return (uint32_t)__cvta_generic_to_shared(p);
}

#define CP_ASYNC16(dst, src) \
    asm volatile("cp.async.cg.shared.global [%0], [%1], 16;\n" :: "r"(dst), "l"(src))
#define CP_COMMIT() asm volatile("cp.async.commit_group;\n" ::: "memory")
#define CP_WAIT(n)  asm volatile("cp.async.wait_group %0;\n" :: "n"(n) : "memory")

// ---------------------------------------------------------------------------
// LIF scan over T=4: v = v + (x - v)/2; spike = v >= 1; hard reset v = 0.
// Exact fp32 ops, identical rounding to reference. Spikes -> fp16 {0,1}.
// One thread handles 4 consecutive d (float4 loads, 8B half stores).
// ---------------------------------------------------------------------------
__global__ __launch_bounds__(256) void spike_kernel(const float* __restrict__ x) {
    int base = (blockIdx.x * 256 + threadIdx.x) * 4;
    float v[4] = {0.f, 0.f, 0.f, 0.f};
#pragma unroll
    for (int t = 0; t < 4; t++) {
        float4 xv = *reinterpret_cast<const float4*>(x + (size_t)t * BND + base);
        float xa[4] = {xv.x, xv.y, xv.z, xv.w};
        __half h[4];
#pragma unroll
        for (int j = 0; j < 4; j++) {
            v[j] = v[j] + (xa[j] - v[j]) * 0.5f;
            bool sp = (v[j] >= 1.0f);
            h[j] = sp ? __float2half_rn(1.0f) : __float2half_rn(0.0f);
            if (sp) v[j] = 0.0f;
        }
        uint2 u;
        u.x = ((uint32_t)__half_as_ushort(h[1]) << 16) | __half_as_ushort(h[0]);
        u.y = ((uint32_t)__half_as_ushort(h[3]) << 16) | __half_as_ushort(h[2]);
        *reinterpret_cast<uint2*>(g_spk + (size_t)t * BND + base) = u;
    }
}

// ---------------------------------------------------------------------------
// W [1000, 512] fp32 -> fp16, zero-padded to [1024, 512]
// ---------------------------------------------------------------------------
__global__ __launch_bounds__(256) void wconv_kernel(const float* __restrict__ W) {
    int base = (blockIdx.x * 256 + threadIdx.x) * 4;   // C_PAD*D/4 = 131072 -> 512 blocks
    int row = base >> 9;                               // /512
    uint2 u;
    if (row < C_DIM) {
        float4 w = *reinterpret_cast<const float4*>(W + base);
        __half h0 = __float2half_rn(w.x), h1 = __float2half_rn(w.y);
        __half h2 = __float2half_rn(w.z), h3 = __float2half_rn(w.w);
        u.x = ((uint32_t)__half_as_ushort(h1) << 16) | __half_as_ushort(h0);
        u.y = ((uint32_t)__half_as_ushort(h3) << 16) | __half_as_ushort(h2);
    } else {
        u.x = 0u; u.y = 0u;
    }
    *reinterpret_cast<uint2*>(g_wh + base) = u;
}

// ---------------------------------------------------------------------------
// GEMM: out[m, c] = sum_k spk[m,k] * W[c,k] + b[c]
// BM=BN=128, BK=32, 8 warps (4x2), warp tile 32x64, mma.m16n8k16 f16->f32.
// Double-buffered cp.async; smem rows padded to 40 halves (conflict-free ldmatrix).
// ---------------------------------------------------------------------------
__global__ __launch_bounds__(256) void gemm_kernel(const float* __restrict__ bias,
                                                   float* __restrict__ out) {
    __shared__ __half sA[2][128 * 40];
    __shared__ __half sB[2][128 * 40];
    __shared__ float sBias[128];

    const int tid = threadIdx.x;
    const int bn = blockIdx.x;   // 8 tiles over C_PAD (fast dim -> L2 reuse of A)
    const int bm = blockIdx.y;   // 392 tiles over M

    if (tid < 128) {
        int c = bn * 128 + tid;
        sBias[tid] = (c < C_DIM) ? bias[c] : 0.f;
    }

    const __half* gA = g_spk + (size_t)bm * 128 * D_DIM;
    const __half* gB = g_wh  + (size_t)bn * 128 * D_DIM;

    // global->smem load mapping: 512 16B vectors per tile, 2 per thread
    const int lrow = tid >> 2;
    const int lcol = (tid & 3) * 8;

    const int warp = tid >> 5;
    const int lane = tid & 31;
    const int wm = warp & 3;      // 4 warps in M
    const int wn = warp >> 2;     // 2 warps in N
    // ldmatrix x4 lane addressing: mat0=(r0-7,k0-7) mat1=(r8-15,k0-7) mat2=(r0-7,k8-15) mat3=(r8-15,k8-15)
    const int mat  = lane >> 3;
    const int rin  = lane & 7;
    const int roff = rin + (mat & 1) * 8;
    const int koff = (mat >> 1) * 8;

    float acc[2][8][4];
#pragma unroll
    for (int i = 0; i < 2; i++)
#pragma unroll
        for (int j = 0; j < 8; j++)
#pragma unroll
            for (int k = 0; k < 4; k++) acc[i][j][k] = 0.f;

    // prologue: stage 0 <- k-tile 0
    {
#pragma unroll
        for (int i = 0; i < 2; i++) {
            int row = lrow + i * 64;
            CP_ASYNC16(smem_u32(&sA[0][row * 40 + lcol]), gA + (size_t)row * D_DIM + lcol);
            CP_ASYNC16(smem_u32(&sB[0][row * 40 + lcol]), gB + (size_t)row * D_DIM + lcol);
        }
        CP_COMMIT();
    }

#pragma unroll 1
    for (int kt = 0; kt < 16; kt++) {
        const int st = kt & 1;
        if (kt < 15) {
            int k0 = (kt + 1) * 32;
#pragma unroll
            for (int i = 0; i < 2; i++) {
                int row = lrow + i * 64;
                CP_ASYNC16(smem_u32(&sA[st ^ 1][row * 40 + lcol]),
                           gA + (size_t)row * D_DIM + k0 + lcol);
                CP_ASYNC16(smem_u32(&sB[st ^ 1][row * 40 + lcol]),
                           gB + (size_t)row * D_DIM + k0 + lcol);
            }
            CP_COMMIT();
            CP_WAIT(1);
        } else {
            CP_WAIT(0);
        }
        __syncthreads();

        const __half* cA = sA[st];
        const __half* cB = sB[st];
#pragma unroll
        for (int ks = 0; ks < 32; ks += 16) {
            uint32_t a[2][4];
#pragma unroll
            for (int mf = 0; mf < 2; mf++) {
                int r = wm * 32 + mf * 16 + roff;
                uint32_t addr = smem_u32(cA + r * 40 + ks + koff);
                asm volatile("ldmatrix.sync.aligned.m8n8.x4.shared.b16 {%0,%1,%2,%3}, [%4];\n"
                             : "=r"(a[mf][0]), "=r"(a[mf][1]), "=r"(a[mf][2]), "=r"(a[mf][3])
                             : "r"(addr));
            }
            uint32_t bq[8][2];
#pragma unroll
            for (int np = 0; np < 4; np++) {
                int r = wn * 64 + np * 16 + roff;
                uint32_t addr = smem_u32(cB + r * 40 + ks + koff);
                uint32_t r0, r1, r2, r3;
                asm volatile("ldmatrix.sync.aligned.m8n8.x4.shared.b16 {%0,%1,%2,%3}, [%4];\n"
                             : "=r"(r0), "=r"(r1), "=r"(r2), "=r"(r3)
                             : "r"(addr));
                bq[2 * np][0] = r0; bq[2 * np + 1][0] = r1;
                bq[2 * np][1] = r2; bq[2 * np + 1][1] = r3;
            }
#pragma unroll
            for (int mf = 0; mf < 2; mf++) {
#pragma unroll
                for (int nf = 0; nf < 8; nf++) {
                    asm volatile(
                        "mma.sync.aligned.m16n8k16.row.col.f32.f16.f16.f32 "
                        "{%0,%1,%2,%3}, {%4,%5,%6,%7}, {%8,%9}, {%0,%1,%2,%3};\n"
                        : "+f"(acc[mf][nf][0]), "+f"(acc[mf][nf][1]),
                          "+f"(acc[mf][nf][2]), "+f"(acc[mf][nf][3])
                        : "r"(a[mf][0]), "r"(a[mf][1]), "r"(a[mf][2]), "r"(a[mf][3]),
                          "r"(bq[nf][0]), "r"(bq[nf][1]));
                }
            }
        }
        __syncthreads();
    }

    // epilogue: +bias, predicated on c < 1000, float2 stores
    const int r  = lane >> 2;
    const int cc = (lane & 3) * 2;
    const int grow = bm * 128 + wm * 32;
    const int gcb  = bn * 128 + wn * 64;
#pragma unroll
    for (int mf = 0; mf < 2; mf++) {
#pragma unroll
        for (int nf = 0; nf < 8; nf++) {
            int col = gcb + nf * 8 + cc;
            if (col < C_DIM) {
                int lc = col - bn * 128;
                float b0 = sBias[lc], b1 = sBias[lc + 1];
                size_t o0 = (size_t)(grow + mf * 16 + r) * C_DIM + col;
                float2 v0 = make_float2(acc[mf][nf][0] + b0, acc[mf][nf][1] + b1);
                float2 v1 = make_float2(acc[mf][nf][2] + b0, acc[mf][nf][3] + b1);
                *reinterpret_cast<float2*>(out + o0) = v0;
                *reinterpret_cast<float2*>(out + o0 + (size_t)8 * C_DIM) = v1;
            }
        }
    }
}

// ---------------------------------------------------------------------------
extern "C" void kernel_launch(void* const* d_in, const int* in_sizes, int n_in,
                              void* d_out, int out_size) {
    const float* x = (const float*)d_in[0];   // [4, 64, 196, 512] fp32
    const float* W = (const float*)d_in[1];   // [1000, 512] fp32
    const float* b = (const float*)d_in[2];   // [1000] fp32
    float* out = (float*)d_out;               // [4, 64, 196, 1000] fp32

    spike_kernel<<<BND / 4 / 256, 256>>>(x);          // 6272 blocks
    wconv_kernel<<<(C_PAD * D_DIM) / 4 / 256, 256>>>(W); // 512 blocks
    gemm_kernel<<<dim3(8, M_ROWS / 128), 256>>>(b, out); // (8, 392)
}